// round 14
// baseline (speedup 1.0000x reference)
#include <cuda_runtime.h>
#include <math.h>

typedef unsigned long long ull;
struct __align__(16) ULL2 { ull x, y; };

#define B_     64
#define F_     4097
#define FCL_   65
#define FL_    64
#define OUT_S  262144
#define NFRB   32          // frames per block
#define NWARP  8
#define ACCLEN 2176        // (NFRB-1)*64 + 192

// ---------------- packed f32x2 helpers ----------------
__device__ __forceinline__ ull fma2_(ull a, ull b, ull c) {
    ull d; asm("fma.rn.f32x2 %0,%1,%2,%3;" : "=l"(d) : "l"(a), "l"(b), "l"(c)); return d;
}
__device__ __forceinline__ ull add2_(ull a, ull b) {
    ull d; asm("add.rn.f32x2 %0,%1,%2;" : "=l"(d) : "l"(a), "l"(b)); return d;
}
__device__ __forceinline__ ull mul2_(ull a, ull b) {
    ull d; asm("mul.rn.f32x2 %0,%1,%2;" : "=l"(d) : "l"(a), "l"(b)); return d;
}
__device__ __forceinline__ ull dup_(float x) {
    ull d; unsigned r = __float_as_uint(x);
    asm("mov.b64 %0,{%1,%1};" : "=l"(d) : "r"(r)); return d;
}
__device__ __forceinline__ void unpk_(ull v, float& lo, float& hi) {
    unsigned a, b; asm("mov.b64 {%0,%1},%2;" : "=r"(a), "=r"(b) : "l"(v));
    lo = __uint_as_float(a); hi = __uint_as_float(b);
}

// ---------------- small precise tables ----------------
__device__ float4 g_rot[32];   // lane l: (cos th*(l+1), sin th*(l+1), cos th*(l+33), sin th*(l+33))
__device__ float  g_win[130];

// prep: build tables AND zero only the block-boundary strips of out
__global__ void prep_k(float4* __restrict__ out4) {
    const int i = blockIdx.x * blockDim.x + threadIdx.x;
    const float TH = 6.283185307179586477f / 129.0f;
    if (i < 32) {
        g_rot[i] = make_float4(cosf(TH * (float)(i + 1)),  sinf(TH * (float)(i + 1)),
                               cosf(TH * (float)(i + 33)), sinf(TH * (float)(i + 33)));
    }
    if (i < 130) g_win[i] = 0.5f - 0.5f * cosf(TH * (float)i);
    if (i < 64 * 128 * 32) {
        const int b  = i >> 12;
        const int r  = i & 4095;
        const int q  = r >> 5;
        const int j4 = r & 31;
        out4[b * 65536 + q * 512 + j4] = make_float4(0.f, 0.f, 0.f, 0.f);
    }
}

__device__ __forceinline__ float msig(float x) {
    float sg = 1.0f / (1.0f + __expf(-x));
    return 2.0f * __powf(sg, 2.302585092994046f) + 1e-7f;
}

// ---------------- wirb XOR swizzle (16B-chunk granularity) ----------------
__device__ __forceinline__ int swz_(int c) { return c ^ ((c >> 3) & 7); }
__device__ __forceinline__ ULL2 wld_(const float* wb, int c) {
    return *(const ULL2*)(wb + (swz_(c) << 2));
}
__device__ __forceinline__ void wst_(float* wb, int i, float v) {
    int c = i >> 2;
    wb[(swz_(c) << 2) | (i & 3)] = v;
}

// ---------------- dynamic smem layout (bytes) ----------------
#define SINTJ_OFF  0        // float[8][65][4] = 8320 (dead after transform -> zp0 scratch)
#define WIR_OFF    8320     // float[8][256]   = 8192 (swizzled; zero outside IR span)
#define OUTB_OFF   16512    // float[32][192]  = 24576 (x in [0..64), zp spill in [128..192))
#define SMEM_TOT   41088    // 40.1 KB -> 5 CTAs/SM

__global__ __launch_bounds__(256, 5) void fn_main(
        const float* __restrict__ coeff,   // (B, F, 65)
        const float* __restrict__ noise,   // (B, F, 64)
        float* __restrict__ out)           // (B, 262144)
{
    extern __shared__ __align__(16) char smdyn[];
    float* sIntJ = (float*)(smdyn + SINTJ_OFF);   // [w][k][ff]
    float* wirb  = (float*)(smdyn + WIR_OFF);     // [w][256] swizzled
    float* outb  = (float*)(smdyn + OUTB_OFF);    // [fi][192]

    const int tid = threadIdx.x;
    const int w   = tid >> 5;
    const int l   = tid & 31;
    const int q   = blockIdx.x;          // 0..127 (frames 0..4095; frame 4096 never contributes)
    const int b   = blockIdx.y;
    const int f0  = q * NFRB;

    // ---- stage inputs, zero wir buffers ----
    for (int i = tid; i < NWARP * 256; i += 256) wirb[i] = 0.f;
    const size_t cbo = ((size_t)b * F_ + f0) * FCL_;
    for (int e = tid; e < NFRB * FCL_; e += 256) {
        int fi = e / 65, k = e - fi * 65;
        sIntJ[(((fi & 7) * 65) + k) * 4 + (fi >> 3)] = msig(coeff[cbo + e]);
    }
    // x staged plain into the first 64 floats of each outb row
    const size_t nbo = ((size_t)b * F_ + f0) * FL_;
    for (int e = tid; e < NFRB * FL_; e += 256) {
        int fi = e >> 6, t = e & 63;
        outb[fi * 192 + t] = 2.f * noise[nbo + e] - 1.f;
    }
    __syncthreads();

    const int t1 = l + 1, t2 = l + 33;
    float* wb = wirb + w * 256;

    // per-lane constants held in registers
    const float4 rt = __ldg(&g_rot[l]);          // (rc1, rs1, rc2, rs2)
    const float w1p = __ldg(&g_win[64 + t1]), w1m = __ldg(&g_win[64 - t1]);
    const float w2p = __ldg(&g_win[64 + t2]), w2m = __ldg(&g_win[64 - t2]);
    const float wc  = __ldg(&g_win[64]);

    // ---- cosine transform via scalar rotation recurrence, 4 frames jointly ----
    // zp[t] = (s0 + 2*sum_{k=1..64} s_k cos(2pi k t/129)) / 129 ; lane handles t1, t2
    float* sw = sIntJ + w * 65 * 4;
    ull ac0AB = 0, ac0CD = 0, ac1AB = 0, ac1CD = 0, ac2AB = 0, ac2CD = 0;
    const ULL2 s0p = *(const ULL2*)sw;
    {
        float c1 = rt.x, s1 = rt.y, c2 = rt.z, s2 = rt.w;   // state at k (seed = k=1)
        ULL2 sp = *(const ULL2*)(sw + 4);                    // k=1, prefetched
        #pragma unroll 8
        for (int k = 1; k <= 64; k++) {
            ULL2 sp_n;
            if (k < 64) sp_n = *(const ULL2*)(sw + (k + 1) * 4);   // prefetch next
            const ull c1d = dup_(c1), c2d = dup_(c2);
            ac1AB = fma2_(sp.x, c1d, ac1AB);  ac1CD = fma2_(sp.y, c1d, ac1CD);
            ac2AB = fma2_(sp.x, c2d, ac2AB);  ac2CD = fma2_(sp.y, c2d, ac2CD);
            ac0AB = add2_(ac0AB, sp.x);       ac0CD = add2_(ac0CD, sp.y);
            const float nc1 = c1 * rt.x - s1 * rt.y;
            const float ns1 = s1 * rt.x + c1 * rt.y;
            c1 = nc1; s1 = ns1;
            const float nc2 = c2 * rt.z - s2 * rt.w;
            const float ns2 = s2 * rt.z + c2 * rt.w;
            c2 = nc2; s2 = ns2;
            if (k < 64) sp = sp_n;
        }
    }
    const ull TWO = dup_(2.0f), SCL = dup_(1.0f / 129.0f);
    {
        // zp0 is lane-invariant and only lane 0 consumes it -> spill to dead sIntJ
        // zp1/zp2 spill through each frame's own row tail (same-lane store/reload)
        float zA, zB;
        ull r;
        r = mul2_(fma2_(ac0AB, TWO, s0p.x), SCL); unpk_(r, zA, zB);
        if (l == 0) { sw[0] = zA; sw[1] = zB; }
        r = mul2_(fma2_(ac0CD, TWO, s0p.y), SCL); unpk_(r, zA, zB);
        if (l == 0) { sw[2] = zA; sw[3] = zB; }
        r = mul2_(fma2_(ac1AB, TWO, s0p.x), SCL); unpk_(r, zA, zB);
        outb[w * 192 + 128 + l] = zA;  outb[(8 + w) * 192 + 128 + l] = zB;
        r = mul2_(fma2_(ac1CD, TWO, s0p.y), SCL); unpk_(r, zA, zB);
        outb[(16 + w) * 192 + 128 + l] = zA;  outb[(24 + w) * 192 + 128 + l] = zB;
        r = mul2_(fma2_(ac2AB, TWO, s0p.x), SCL); unpk_(r, zA, zB);
        outb[w * 192 + 160 + l] = zA;  outb[(8 + w) * 192 + 160 + l] = zB;
        r = mul2_(fma2_(ac2CD, TWO, s0p.y), SCL); unpk_(r, zA, zB);
        outb[(16 + w) * 192 + 160 + l] = zA;  outb[(24 + w) * 192 + 160 + l] = zB;
    }

    // ---- per-frame: windowed IR build + 64x192 linear conv (dual-phase, even pairs) ----
    #pragma unroll
    for (int ff = 0; ff < 4; ff++) {
        const int fi = ff * NWARP + w;
        const float zp1 = outb[fi * 192 + 128 + l];   // same-lane reload
        const float zp2 = outb[fi * 192 + 160 + l];

        // wb[128 +/- t] = win * zp (zp even-symmetric)
        wst_(wb, 128 + t1, w1p * zp1);
        wst_(wb, 128 - t1, w1m * zp1);
        wst_(wb, 128 + t2, w2p * zp2);
        wst_(wb, 128 - t2, w2m * zp2);
        if (l == 0) wst_(wb, 128, wc * sw[ff]);   // lane-0 same-lane scratch reload
        __syncwarp();

        // lane ll owns outputs t = 8ll..8ll+7 (ll<24); lane 24 = boundary producer.
        const float* xs = outb + fi * 192;
        const int ll = (l < 25) ? l : 0;
        ull a0 = 0, a1 = 0, a2 = 0, a3 = 0;
        ull b0 = 0, b1 = 0, b2 = 0, b3 = 0;
        ull v0, v1, v2, v3, v4, v5;   // pairs (B-2 .. B+3), B = 32+4*ll-2g
        {
            const ULL2 pa = wld_(wb, 15 + 2 * ll);
            const ULL2 pb = wld_(wb, 16 + 2 * ll);
            const ULL2 pc = wld_(wb, 17 + 2 * ll);
            v0 = pa.x; v1 = pa.y; v2 = pb.x; v3 = pb.y; v4 = pc.x; v5 = pc.y;
        }
        float4 xq = *(const float4*)(xs);   // g=0, prefetched
        #pragma unroll
        for (int g = 0; g < 16; g++) {
            float4 xq_n;
            ULL2 nw;
            if (g < 15) {                                // prefetch next iteration's data
                xq_n = *(const float4*)(xs + 4 * (g + 1));
                nw = wld_(wb, 14 + 2 * ll - g);
            }
            const ull x0 = dup_(xq.x), x1 = dup_(xq.y), x2 = dup_(xq.z), x3 = dup_(xq.w);
            a0 = fma2_(x0, v2, a0); a1 = fma2_(x0, v3, a1);
            a2 = fma2_(x0, v4, a2); a3 = fma2_(x0, v5, a3);
            b0 = fma2_(x1, v1, b0); b1 = fma2_(x1, v2, b1);
            b2 = fma2_(x1, v3, b2); b3 = fma2_(x1, v4, b3);
            a0 = fma2_(x2, v1, a0); a1 = fma2_(x2, v2, a1);
            a2 = fma2_(x2, v3, a2); a3 = fma2_(x2, v4, a3);
            b0 = fma2_(x3, v0, b0); b1 = fma2_(x3, v1, b1);
            b2 = fma2_(x3, v2, b2); b3 = fma2_(x3, v3, b3);
            if (g < 15) {
                v5 = v3; v4 = v2; v3 = v1; v2 = v0;
                v1 = nw.y; v0 = nw.x;
                xq = xq_n;
            }
        }
        // combine phases; one cross-lane boundary term via shfl
        float aL0, aH0, aL1, aH1, aL2, aH2, aL3, aH3;
        float bL0, bH0, bL1, bH1, bL2, bH2, bL3, bH3;
        unpk_(a0, aL0, aH0); unpk_(a1, aL1, aH1);
        unpk_(a2, aL2, aH2); unpk_(a3, aL3, aH3);
        unpk_(b0, bL0, bH0); unpk_(b1, bL1, bH1);
        unpk_(b2, bL2, bH2); unpk_(b3, bL3, bH3);
        const float up = __shfl_down_sync(0xffffffffu, bL0, 1);
        __syncwarp();   // all lanes' reads of wb/xs done before overwrite below / next wst
        if (l < 24) {
            float4 o03, o47;
            o03.x = aL0 + bH0; o03.y = aH0 + bL1;
            o03.z = aL1 + bH1; o03.w = aH1 + bL2;
            o47.x = aL2 + bH2; o47.y = aH2 + bL3;
            o47.z = aL3 + bH3; o47.w = aH3 + up;
            float4* op = (float4*)(outb + fi * 192 + 8 * l);
            op[0] = o03;
            op[1] = o47;
        }
        // no trailing syncwarp: next frame's wst targets wb (reads done at the sync
        // above); this row store and next frame's conv touch disjoint outb rows.
    }

    __syncthreads();

    // ---- overlap-add: interior exclusively owned, boundaries via atomics ----
    const size_t rowb = (size_t)b * OUT_S;
    const int gb = f0 * FL_;
    for (int p = tid; p < ACCLEN; p += 256) {
        const int P = gb + p;
        if (P >= OUT_S) continue;
        const int fhi = p >> 6;
        const int t0  = p & 63;
        float v = 0.f;
        if (fhi < NFRB)                 v += outb[fhi * 192 + t0];
        if (fhi >= 1 && fhi - 1 < NFRB) v += outb[(fhi - 1) * 192 + t0 + 64];
        if (fhi >= 2 && fhi - 2 < NFRB) v += outb[(fhi - 2) * 192 + t0 + 128];
        if (p >= 128 && p < 2048) out[rowb + P] = v;
        else                      atomicAdd(&out[rowb + P], v);
    }
}

extern "C" void kernel_launch(void* const* d_in, const int* in_sizes, int n_in,
                              void* d_out, int out_size) {
    const float* coeff = (const float*)d_in[0];
    const float* noise = (const float*)d_in[1];
    float* out = (float*)d_out;

    cudaFuncSetAttribute(fn_main, cudaFuncAttributeMaxDynamicSharedMemorySize, SMEM_TOT);
    prep_k<<<1024, 256>>>((float4*)out);
    dim3 grid(128, B_);
    fn_main<<<grid, 256, SMEM_TOT>>>(coeff, noise, out);
}

// round 15
// speedup vs baseline: 1.0276x; 1.0276x over previous
#include <cuda_runtime.h>
#include <math.h>

typedef unsigned long long ull;
struct __align__(16) ULL2 { ull x, y; };

#define B_     64
#define F_     4097
#define FCL_   65
#define FL_    64
#define OUT_S  262144
#define NFRB   32          // frames per block
#define NWARP  8
#define ACCLEN 2176        // (NFRB-1)*64 + 192

// ---------------- packed f32x2 helpers ----------------
__device__ __forceinline__ ull fma2_(ull a, ull b, ull c) {
    ull d; asm("fma.rn.f32x2 %0,%1,%2,%3;" : "=l"(d) : "l"(a), "l"(b), "l"(c)); return d;
}
__device__ __forceinline__ ull add2_(ull a, ull b) {
    ull d; asm("add.rn.f32x2 %0,%1,%2;" : "=l"(d) : "l"(a), "l"(b)); return d;
}
__device__ __forceinline__ ull mul2_(ull a, ull b) {
    ull d; asm("mul.rn.f32x2 %0,%1,%2;" : "=l"(d) : "l"(a), "l"(b)); return d;
}
__device__ __forceinline__ ull dup_(float x) {
    ull d; unsigned r = __float_as_uint(x);
    asm("mov.b64 %0,{%1,%1};" : "=l"(d) : "r"(r)); return d;
}
__device__ __forceinline__ void unpk_(ull v, float& lo, float& hi) {
    unsigned a, b; asm("mov.b64 {%0,%1},%2;" : "=r"(a), "=r"(b) : "l"(v));
    lo = __uint_as_float(a); hi = __uint_as_float(b);
}

// ---------------- small precise tables ----------------
// g_rot[l] = (cos th1, cos th2, 2cos th1, 2cos th2), th1 = TH*(l+1), th2 = TH*(l+33)
// g_chk[j*32+l] = (cos k0*th1, cos (k0+1)*th1, cos k0*th2, cos (k0+1)*th2), k0 = 16*(j+1)
__device__ float4 g_rot[32];
__device__ float4 g_chk[3 * 32];
__device__ float  g_win[130];

// prep: build tables AND zero only the block-boundary strips of out
__global__ void prep_k(float4* __restrict__ out4) {
    const int i = blockIdx.x * blockDim.x + threadIdx.x;
    const float TH = 6.283185307179586477f / 129.0f;
    if (i < 32) {
        const int ta = i + 1, tb = i + 33;
        const float c1 = cosf(TH * (float)ta), c2 = cosf(TH * (float)tb);
        g_rot[i] = make_float4(c1, c2, 2.f * c1, 2.f * c2);
        #pragma unroll
        for (int j = 0; j < 3; j++) {
            const int k0 = 16 * (j + 1);
            g_chk[j * 32 + i] = make_float4(
                cosf(TH * (float)((k0 * ta) % 129)),
                cosf(TH * (float)(((k0 + 1) * ta) % 129)),
                cosf(TH * (float)((k0 * tb) % 129)),
                cosf(TH * (float)(((k0 + 1) * tb) % 129)));
        }
    }
    if (i < 130) g_win[i] = 0.5f - 0.5f * cosf(TH * (float)i);
    if (i < 64 * 128 * 32) {
        const int b  = i >> 12;
        const int r  = i & 4095;
        const int q  = r >> 5;
        const int j4 = r & 31;
        out4[b * 65536 + q * 512 + j4] = make_float4(0.f, 0.f, 0.f, 0.f);
    }
}

__device__ __forceinline__ float msig(float x) {
    float sg = 1.0f / (1.0f + __expf(-x));
    return 2.0f * __powf(sg, 2.302585092994046f) + 1e-7f;
}

// ---------------- wirb XOR swizzle (16B-chunk granularity) ----------------
__device__ __forceinline__ int swz_(int c) { return c ^ ((c >> 3) & 7); }
__device__ __forceinline__ ULL2 wld_(const float* wb, int c) {
    return *(const ULL2*)(wb + (swz_(c) << 2));
}
__device__ __forceinline__ void wst_(float* wb, int i, float v) {
    int c = i >> 2;
    wb[(swz_(c) << 2) | (i & 3)] = v;
}

// ---------------- dynamic smem layout (bytes) ----------------
#define SINTJ_OFF  0        // float[8][65][4] = 8320
#define WIR_OFF    8320     // float[8][256]   = 8192 (swizzled; zero outside IR span)
#define OUTB_OFF   16512    // float[32][192]  = 24576 (x in [0..64), zp spill in [128..192))
#define SMEM_TOT   41088    // 40.1 KB -> 5 CTAs/SM

__global__ __launch_bounds__(256, 5) void fn_main(
        const float* __restrict__ coeff,   // (B, F, 65)
        const float* __restrict__ noise,   // (B, F, 64)
        float* __restrict__ out)           // (B, 262144)
{
    extern __shared__ __align__(16) char smdyn[];
    float* sIntJ = (float*)(smdyn + SINTJ_OFF);   // [w][k][ff]
    float* wirb  = (float*)(smdyn + WIR_OFF);     // [w][256] swizzled
    float* outb  = (float*)(smdyn + OUTB_OFF);    // [fi][192]

    const int tid = threadIdx.x;
    const int w   = tid >> 5;
    const int l   = tid & 31;
    const int q   = blockIdx.x;          // 0..127 (frames 0..4095; frame 4096 never contributes)
    const int b   = blockIdx.y;
    const int f0  = q * NFRB;

    // ---- stage inputs, zero wir buffers ----
    for (int i = tid; i < NWARP * 256; i += 256) wirb[i] = 0.f;
    const size_t cbo = ((size_t)b * F_ + f0) * FCL_;
    for (int e = tid; e < NFRB * FCL_; e += 256) {
        int fi = e / 65, k = e - fi * 65;
        sIntJ[(((fi & 7) * 65) + k) * 4 + (fi >> 3)] = msig(coeff[cbo + e]);
    }
    // x staged plain into the first 64 floats of each outb row
    const size_t nbo = ((size_t)b * F_ + f0) * FL_;
    for (int e = tid; e < NFRB * FL_; e += 256) {
        int fi = e >> 6, t = e & 63;
        outb[fi * 192 + t] = 2.f * noise[nbo + e] - 1.f;
    }
    __syncthreads();

    const int t1 = l + 1, t2 = l + 33;
    float* wb = wirb + w * 256;

    // per-lane constants held in registers
    const float4 rt = __ldg(&g_rot[l]);          // (c1, c2, 2c1, 2c2)
    const float w1p = __ldg(&g_win[64 + t1]), w1m = __ldg(&g_win[64 - t1]);
    const float w2p = __ldg(&g_win[64 + t2]), w2m = __ldg(&g_win[64 - t2]);
    const float wc  = __ldg(&g_win[64]);

    // ---- cosine transform via Chebyshev 3-term recurrence (exact reseed /16 steps) ----
    // zp[t] = (s0 + 2*sum_{k=1..64} s_k cos(2pi k t/129)) / 129 ; lane handles t1, t2
    const float* sw = sIntJ + w * 65 * 4;
    ull ac0AB = 0, ac0CD = 0, ac1AB = 0, ac1CD = 0, ac2AB = 0, ac2CD = 0;
    const ULL2 s0p = *(const ULL2*)sw;
    {
        const float tc1 = rt.z, tc2 = rt.w;      // 2cos(theta)
        float cp1 = 1.f, c1 = rt.x;              // cos((k-1)th1), cos(k th1) at k=1
        float cp2 = 1.f, c2 = rt.y;
        #pragma unroll
        for (int seg = 0; seg < 4; seg++) {
            if (seg > 0) {                        // exact reseed: kills drift growth
                const float4 ck = __ldg(&g_chk[(seg - 1) * 32 + l]);
                cp1 = ck.x; c1 = ck.y; cp2 = ck.z; c2 = ck.w;
            }
            #pragma unroll
            for (int r16 = 0; r16 < 16; r16++) {
                const int k = seg * 16 + r16 + 1;
                const ULL2 sp = *(const ULL2*)(sw + k * 4);   // broadcast LDS.128
                const ull c1d = dup_(c1), c2d = dup_(c2);
                ac1AB = fma2_(sp.x, c1d, ac1AB);  ac1CD = fma2_(sp.y, c1d, ac1CD);
                ac2AB = fma2_(sp.x, c2d, ac2AB);  ac2CD = fma2_(sp.y, c2d, ac2CD);
                ac0AB = add2_(ac0AB, sp.x);       ac0CD = add2_(ac0CD, sp.y);
                const float cn1 = fmaf(tc1, c1, -cp1);   // cos((k+1)th) = 2c*ck - ck-1
                cp1 = c1; c1 = cn1;
                const float cn2 = fmaf(tc2, c2, -cp2);
                cp2 = c2; c2 = cn2;
            }
        }
    }
    const ull TWO = dup_(2.0f), SCL = dup_(1.0f / 129.0f);
    float zp0s[4];
    {
        // zp1/zp2 spill through each frame's own row tail (same-lane store/reload)
        float zA, zB;
        ull r;
        r = mul2_(fma2_(ac0AB, TWO, s0p.x), SCL); unpk_(r, zp0s[0], zp0s[1]);
        r = mul2_(fma2_(ac0CD, TWO, s0p.y), SCL); unpk_(r, zp0s[2], zp0s[3]);
        r = mul2_(fma2_(ac1AB, TWO, s0p.x), SCL); unpk_(r, zA, zB);
        outb[w * 192 + 128 + l] = zA;  outb[(8 + w) * 192 + 128 + l] = zB;
        r = mul2_(fma2_(ac1CD, TWO, s0p.y), SCL); unpk_(r, zA, zB);
        outb[(16 + w) * 192 + 128 + l] = zA;  outb[(24 + w) * 192 + 128 + l] = zB;
        r = mul2_(fma2_(ac2AB, TWO, s0p.x), SCL); unpk_(r, zA, zB);
        outb[w * 192 + 160 + l] = zA;  outb[(8 + w) * 192 + 160 + l] = zB;
        r = mul2_(fma2_(ac2CD, TWO, s0p.y), SCL); unpk_(r, zA, zB);
        outb[(16 + w) * 192 + 160 + l] = zA;  outb[(24 + w) * 192 + 160 + l] = zB;
    }

    // ---- per-frame: windowed IR build + 64x192 linear conv (dual-phase, even pairs) ----
    #pragma unroll
    for (int ff = 0; ff < 4; ff++) {
        const int fi = ff * NWARP + w;
        const float zp1 = outb[fi * 192 + 128 + l];   // same-lane reload
        const float zp2 = outb[fi * 192 + 160 + l];

        // wb[128 +/- t] = win * zp (zp even-symmetric)
        wst_(wb, 128 + t1, w1p * zp1);
        wst_(wb, 128 - t1, w1m * zp1);
        wst_(wb, 128 + t2, w2p * zp2);
        wst_(wb, 128 - t2, w2m * zp2);
        if (l == 0) wst_(wb, 128, wc * zp0s[ff]);
        __syncwarp();

        // lane ll owns outputs t = 8ll..8ll+7 (ll<24); lane 24 = boundary producer.
        const float* xs = outb + fi * 192;
        const int ll = (l < 25) ? l : 0;
        ull a0 = 0, a1 = 0, a2 = 0, a3 = 0;
        ull b0 = 0, b1 = 0, b2 = 0, b3 = 0;
        ull v0, v1, v2, v3, v4, v5;   // pairs (B-2 .. B+3), B = 32+4*ll-2g
        {
            const ULL2 pa = wld_(wb, 15 + 2 * ll);
            const ULL2 pb = wld_(wb, 16 + 2 * ll);
            const ULL2 pc = wld_(wb, 17 + 2 * ll);
            v0 = pa.x; v1 = pa.y; v2 = pb.x; v3 = pb.y; v4 = pc.x; v5 = pc.y;
        }
        #pragma unroll
        for (int g = 0; g < 16; g++) {
            const float4 xq = *(const float4*)(xs + 4 * g);
            const ull x0 = dup_(xq.x), x1 = dup_(xq.y), x2 = dup_(xq.z), x3 = dup_(xq.w);
            a0 = fma2_(x0, v2, a0); a1 = fma2_(x0, v3, a1);
            a2 = fma2_(x0, v4, a2); a3 = fma2_(x0, v5, a3);
            b0 = fma2_(x1, v1, b0); b1 = fma2_(x1, v2, b1);
            b2 = fma2_(x1, v3, b2); b3 = fma2_(x1, v4, b3);
            a0 = fma2_(x2, v1, a0); a1 = fma2_(x2, v2, a1);
            a2 = fma2_(x2, v3, a2); a3 = fma2_(x2, v4, a3);
            b0 = fma2_(x3, v0, b0); b1 = fma2_(x3, v1, b1);
            b2 = fma2_(x3, v2, b2); b3 = fma2_(x3, v3, b3);
            if (g < 15) {
                const ULL2 nw = wld_(wb, 14 + 2 * ll - g);
                v5 = v3; v4 = v2; v3 = v1; v2 = v0;
                v1 = nw.y; v0 = nw.x;
            }
        }
        // combine phases; one cross-lane boundary term via shfl
        float aL0, aH0, aL1, aH1, aL2, aH2, aL3, aH3;
        float bL0, bH0, bL1, bH1, bL2, bH2, bL3, bH3;
        unpk_(a0, aL0, aH0); unpk_(a1, aL1, aH1);
        unpk_(a2, aL2, aH2); unpk_(a3, aL3, aH3);
        unpk_(b0, bL0, bH0); unpk_(b1, bL1, bH1);
        unpk_(b2, bL2, bH2); unpk_(b3, bL3, bH3);
        const float up = __shfl_down_sync(0xffffffffu, bL0, 1);
        __syncwarp();   // all lanes' reads of wb/xs done before overwrite below / next wst
        if (l < 24) {
            float4 o03, o47;
            o03.x = aL0 + bH0; o03.y = aH0 + bL1;
            o03.z = aL1 + bH1; o03.w = aH1 + bL2;
            o47.x = aL2 + bH2; o47.y = aH2 + bL3;
            o47.z = aL3 + bH3; o47.w = aH3 + up;
            float4* op = (float4*)(outb + fi * 192 + 8 * l);
            op[0] = o03;
            op[1] = o47;
        }
        // no trailing syncwarp: next frame's wst targets wb (reads done at the sync
        // above); this row store and next frame's conv touch disjoint outb rows.
    }

    __syncthreads();

    // ---- overlap-add: interior exclusively owned, boundaries via atomics ----
    const size_t rowb = (size_t)b * OUT_S;
    const int gb = f0 * FL_;
    for (int p = tid; p < ACCLEN; p += 256) {
        const int P = gb + p;
        if (P >= OUT_S) continue;
        const int fhi = p >> 6;
        const int t0  = p & 63;
        float v = 0.f;
        if (fhi < NFRB)                 v += outb[fhi * 192 + t0];
        if (fhi >= 1 && fhi - 1 < NFRB) v += outb[(fhi - 1) * 192 + t0 + 64];
        if (fhi >= 2 && fhi - 2 < NFRB) v += outb[(fhi - 2) * 192 + t0 + 128];
        if (p >= 128 && p < 2048) out[rowb + P] = v;
        else                      atomicAdd(&out[rowb + P], v);
    }
}

extern "C" void kernel_launch(void* const* d_in, const int* in_sizes, int n_in,
                              void* d_out, int out_size) {
    const float* coeff = (const float*)d_in[0];
    const float* noise = (const float*)d_in[1];
    float* out = (float*)d_out;

    cudaFuncSetAttribute(fn_main, cudaFuncAttributeMaxDynamicSharedMemorySize, SMEM_TOT);
    prep_k<<<1024, 256>>>((float4*)out);
    dim3 grid(128, B_);
    fn_main<<<grid, 256, SMEM_TOT>>>(coeff, noise, out);
}

// round 16
// speedup vs baseline: 1.0429x; 1.0148x over previous
#include <cuda_runtime.h>
#include <math.h>

typedef unsigned long long ull;
struct __align__(16) ULL2 { ull x, y; };

#define B_     64
#define F_     4097
#define FCL_   65
#define FL_    64
#define OUT_S  262144
#define NFRB   32          // frames per block
#define NWARP  8

// ---------------- packed f32x2 helpers ----------------
__device__ __forceinline__ ull fma2_(ull a, ull b, ull c) {
    ull d; asm("fma.rn.f32x2 %0,%1,%2,%3;" : "=l"(d) : "l"(a), "l"(b), "l"(c)); return d;
}
__device__ __forceinline__ ull add2_(ull a, ull b) {
    ull d; asm("add.rn.f32x2 %0,%1,%2;" : "=l"(d) : "l"(a), "l"(b)); return d;
}
__device__ __forceinline__ ull mul2_(ull a, ull b) {
    ull d; asm("mul.rn.f32x2 %0,%1,%2;" : "=l"(d) : "l"(a), "l"(b)); return d;
}
__device__ __forceinline__ ull dup_(float x) {
    ull d; unsigned r = __float_as_uint(x);
    asm("mov.b64 %0,{%1,%1};" : "=l"(d) : "r"(r)); return d;
}
__device__ __forceinline__ void unpk_(ull v, float& lo, float& hi) {
    unsigned a, b; asm("mov.b64 {%0,%1},%2;" : "=r"(a), "=r"(b) : "l"(v));
    lo = __uint_as_float(a); hi = __uint_as_float(b);
}

// ---------------- small precise tables ----------------
// g_rot[l] = (cos th1, cos th2, 2cos th1, 2cos th2), th1 = TH*(l+1), th2 = TH*(l+33)
// g_chk[j*32+l] = (cos k0*th1, cos (k0+1)*th1, cos k0*th2, cos (k0+1)*th2), k0 = 16*(j+1)
__device__ float4 g_rot[32];
__device__ float4 g_chk[3 * 32];
__device__ float  g_win[130];

// prep: build tables AND zero only the block-boundary strips of out
__global__ void prep_k(float4* __restrict__ out4) {
    const int i = blockIdx.x * blockDim.x + threadIdx.x;
    const float TH = 6.283185307179586477f / 129.0f;
    if (i < 32) {
        const int ta = i + 1, tb = i + 33;
        const float c1 = cosf(TH * (float)ta), c2 = cosf(TH * (float)tb);
        g_rot[i] = make_float4(c1, c2, 2.f * c1, 2.f * c2);
        #pragma unroll
        for (int j = 0; j < 3; j++) {
            const int k0 = 16 * (j + 1);
            g_chk[j * 32 + i] = make_float4(
                cosf(TH * (float)((k0 * ta) % 129)),
                cosf(TH * (float)(((k0 + 1) * ta) % 129)),
                cosf(TH * (float)((k0 * tb) % 129)),
                cosf(TH * (float)(((k0 + 1) * tb) % 129)));
        }
    }
    if (i < 130) g_win[i] = 0.5f - 0.5f * cosf(TH * (float)i);
    if (i < 64 * 128 * 32) {
        const int b  = i >> 12;
        const int r  = i & 4095;
        const int q  = r >> 5;
        const int j4 = r & 31;
        out4[b * 65536 + q * 512 + j4] = make_float4(0.f, 0.f, 0.f, 0.f);
    }
}

__device__ __forceinline__ float msig(float x) {
    float sg = __fdividef(1.0f, 1.0f + __expf(-x));
    return 2.0f * __powf(sg, 2.302585092994046f) + 1e-7f;
}

// ---------------- wirb XOR swizzle (16B-chunk granularity) ----------------
__device__ __forceinline__ int swz_(int c) { return c ^ ((c >> 3) & 7); }
__device__ __forceinline__ ULL2 wld_(const float* wb, int c) {
    return *(const ULL2*)(wb + (swz_(c) << 2));
}
__device__ __forceinline__ void wst_(float* wb, int i, float v) {
    int c = i >> 2;
    wb[(swz_(c) << 2) | (i & 3)] = v;
}

// ---------------- dynamic smem layout (bytes) ----------------
#define SINTJ_OFF  0        // float[8][65][4] = 8320
#define WIR_OFF    8320     // float[8][256]   = 8192 (swizzled; zero outside IR span)
#define OUTB_OFF   16512    // float[32][192]  = 24576 (x in [0..64), zp spill in [128..192))
#define SMEM_TOT   41088    // 40.1 KB -> 5 CTAs/SM

__global__ __launch_bounds__(256, 5) void fn_main(
        const float* __restrict__ coeff,   // (B, F, 65)
        const float* __restrict__ noise,   // (B, F, 64)
        float* __restrict__ out)           // (B, 262144)
{
    extern __shared__ __align__(16) char smdyn[];
    float* sIntJ = (float*)(smdyn + SINTJ_OFF);   // [w][k][ff]
    float* wirb  = (float*)(smdyn + WIR_OFF);     // [w][256] swizzled
    float* outb  = (float*)(smdyn + OUTB_OFF);    // [fi][192]

    const int tid = threadIdx.x;
    const int w   = tid >> 5;
    const int l   = tid & 31;
    const int q   = blockIdx.x;          // 0..127 (frames 0..4095; frame 4096 never contributes)
    const int b   = blockIdx.y;
    const int f0  = q * NFRB;

    // ---- stage inputs, zero wir buffers ----
    for (int i = tid; i < NWARP * 256; i += 256) wirb[i] = 0.f;
    const size_t cbo = ((size_t)b * F_ + f0) * FCL_;
    {
        int fi = tid / 65, k = tid - fi * 65;   // one division per thread
        for (int e = tid; e < NFRB * FCL_; e += 256) {
            sIntJ[(((fi & 7) * 65) + k) * 4 + (fi >> 3)] = msig(coeff[cbo + e]);
            fi += 3; k += 61;                   // 256 = 3*65 + 61
            if (k >= 65) { k -= 65; fi++; }
        }
    }
    // x staged plain into the first 64 floats of each outb row
    const size_t nbo = ((size_t)b * F_ + f0) * FL_;
    for (int e = tid; e < NFRB * FL_; e += 256) {
        int fi = e >> 6, t = e & 63;
        outb[fi * 192 + t] = 2.f * noise[nbo + e] - 1.f;
    }
    __syncthreads();

    const int t1 = l + 1, t2 = l + 33;
    float* wb = wirb + w * 256;

    // per-lane constants held in registers
    const float4 rt = __ldg(&g_rot[l]);          // (c1, c2, 2c1, 2c2)
    const float w1p = __ldg(&g_win[64 + t1]), w1m = __ldg(&g_win[64 - t1]);
    const float w2p = __ldg(&g_win[64 + t2]), w2m = __ldg(&g_win[64 - t2]);
    const float wc  = __ldg(&g_win[64]);

    // ---- cosine transform via Chebyshev 3-term recurrence (exact reseed /16 steps) ----
    // zp[t] = (s0 + 2*sum_{k=1..64} s_k cos(2pi k t/129)) / 129 ; lane handles t1, t2
    const float* sw = sIntJ + w * 65 * 4;
    ull ac0AB = 0, ac0CD = 0, ac1AB = 0, ac1CD = 0, ac2AB = 0, ac2CD = 0;
    const ULL2 s0p = *(const ULL2*)sw;
    {
        const float tc1 = rt.z, tc2 = rt.w;      // 2cos(theta)
        float cp1 = 1.f, c1 = rt.x;              // cos((k-1)th1), cos(k th1) at k=1
        float cp2 = 1.f, c2 = rt.y;
        #pragma unroll
        for (int seg = 0; seg < 4; seg++) {
            if (seg > 0) {                        // exact reseed: kills drift growth
                const float4 ck = __ldg(&g_chk[(seg - 1) * 32 + l]);
                cp1 = ck.x; c1 = ck.y; cp2 = ck.z; c2 = ck.w;
            }
            #pragma unroll
            for (int r16 = 0; r16 < 16; r16++) {
                const int k = seg * 16 + r16 + 1;
                const ULL2 sp = *(const ULL2*)(sw + k * 4);   // broadcast LDS.128
                const ull c1d = dup_(c1), c2d = dup_(c2);
                ac1AB = fma2_(sp.x, c1d, ac1AB);  ac1CD = fma2_(sp.y, c1d, ac1CD);
                ac2AB = fma2_(sp.x, c2d, ac2AB);  ac2CD = fma2_(sp.y, c2d, ac2CD);
                ac0AB = add2_(ac0AB, sp.x);       ac0CD = add2_(ac0CD, sp.y);
                const float cn1 = fmaf(tc1, c1, -cp1);   // cos((k+1)th) = 2c*ck - ck-1
                cp1 = c1; c1 = cn1;
                const float cn2 = fmaf(tc2, c2, -cp2);
                cp2 = c2; c2 = cn2;
            }
        }
    }
    const ull TWO = dup_(2.0f), SCL = dup_(1.0f / 129.0f);
    float zp0s[4];
    {
        // zp1/zp2 spill through each frame's own row tail (same-lane store/reload)
        float zA, zB;
        ull r;
        r = mul2_(fma2_(ac0AB, TWO, s0p.x), SCL); unpk_(r, zp0s[0], zp0s[1]);
        r = mul2_(fma2_(ac0CD, TWO, s0p.y), SCL); unpk_(r, zp0s[2], zp0s[3]);
        r = mul2_(fma2_(ac1AB, TWO, s0p.x), SCL); unpk_(r, zA, zB);
        outb[w * 192 + 128 + l] = zA;  outb[(8 + w) * 192 + 128 + l] = zB;
        r = mul2_(fma2_(ac1CD, TWO, s0p.y), SCL); unpk_(r, zA, zB);
        outb[(16 + w) * 192 + 128 + l] = zA;  outb[(24 + w) * 192 + 128 + l] = zB;
        r = mul2_(fma2_(ac2AB, TWO, s0p.x), SCL); unpk_(r, zA, zB);
        outb[w * 192 + 160 + l] = zA;  outb[(8 + w) * 192 + 160 + l] = zB;
        r = mul2_(fma2_(ac2CD, TWO, s0p.y), SCL); unpk_(r, zA, zB);
        outb[(16 + w) * 192 + 160 + l] = zA;  outb[(24 + w) * 192 + 160 + l] = zB;
    }

    // ---- per-frame: windowed IR build + 64x192 linear conv (dual-phase, even pairs) ----
    #pragma unroll
    for (int ff = 0; ff < 4; ff++) {
        const int fi = ff * NWARP + w;
        const float zp1 = outb[fi * 192 + 128 + l];   // same-lane reload
        const float zp2 = outb[fi * 192 + 160 + l];

        // wb[128 +/- t] = win * zp (zp even-symmetric)
        wst_(wb, 128 + t1, w1p * zp1);
        wst_(wb, 128 - t1, w1m * zp1);
        wst_(wb, 128 + t2, w2p * zp2);
        wst_(wb, 128 - t2, w2m * zp2);
        if (l == 0) wst_(wb, 128, wc * zp0s[ff]);
        __syncwarp();

        // lane ll owns outputs t = 8ll..8ll+7 (ll<24); lane 24 = boundary producer.
        const float* xs = outb + fi * 192;
        const int ll = (l < 25) ? l : 0;
        ull a0 = 0, a1 = 0, a2 = 0, a3 = 0;
        ull b0 = 0, b1 = 0, b2 = 0, b3 = 0;
        ull v0, v1, v2, v3, v4, v5;   // pairs (B-2 .. B+3), B = 32+4*ll-2g
        {
            const ULL2 pa = wld_(wb, 15 + 2 * ll);
            const ULL2 pb = wld_(wb, 16 + 2 * ll);
            const ULL2 pc = wld_(wb, 17 + 2 * ll);
            v0 = pa.x; v1 = pa.y; v2 = pb.x; v3 = pb.y; v4 = pc.x; v5 = pc.y;
        }
        #pragma unroll
        for (int g = 0; g < 16; g++) {
            const float4 xq = *(const float4*)(xs + 4 * g);
            const ull x0 = dup_(xq.x), x1 = dup_(xq.y), x2 = dup_(xq.z), x3 = dup_(xq.w);
            a0 = fma2_(x0, v2, a0); a1 = fma2_(x0, v3, a1);
            a2 = fma2_(x0, v4, a2); a3 = fma2_(x0, v5, a3);
            b0 = fma2_(x1, v1, b0); b1 = fma2_(x1, v2, b1);
            b2 = fma2_(x1, v3, b2); b3 = fma2_(x1, v4, b3);
            a0 = fma2_(x2, v1, a0); a1 = fma2_(x2, v2, a1);
            a2 = fma2_(x2, v3, a2); a3 = fma2_(x2, v4, a3);
            b0 = fma2_(x3, v0, b0); b1 = fma2_(x3, v1, b1);
            b2 = fma2_(x3, v2, b2); b3 = fma2_(x3, v3, b3);
            if (g < 15) {
                const ULL2 nw = wld_(wb, 14 + 2 * ll - g);
                v5 = v3; v4 = v2; v3 = v1; v2 = v0;
                v1 = nw.y; v0 = nw.x;
            }
        }
        // combine phases; one cross-lane boundary term via shfl
        float aL0, aH0, aL1, aH1, aL2, aH2, aL3, aH3;
        float bL0, bH0, bL1, bH1, bL2, bH2, bL3, bH3;
        unpk_(a0, aL0, aH0); unpk_(a1, aL1, aH1);
        unpk_(a2, aL2, aH2); unpk_(a3, aL3, aH3);
        unpk_(b0, bL0, bH0); unpk_(b1, bL1, bH1);
        unpk_(b2, bL2, bH2); unpk_(b3, bL3, bH3);
        const float up = __shfl_down_sync(0xffffffffu, bL0, 1);
        __syncwarp();   // all lanes' reads of wb/xs done before overwrite below / next wst
        if (l < 24) {
            float4 o03, o47;
            o03.x = aL0 + bH0; o03.y = aH0 + bL1;
            o03.z = aL1 + bH1; o03.w = aH1 + bL2;
            o47.x = aL2 + bH2; o47.y = aH2 + bL3;
            o47.z = aL3 + bH3; o47.w = aH3 + up;
            float4* op = (float4*)(outb + fi * 192 + 8 * l);
            op[0] = o03;
            op[1] = o47;
        }
        // no trailing syncwarp: next frame's wst targets wb (reads done at the sync
        // above); this row store and next frame's conv touch disjoint outb rows.
    }

    __syncthreads();

    // ---- overlap-add ----
    const size_t rowb = (size_t)b * OUT_S;
    const int gb = f0 * FL_;
    // interior [128, 2048): exclusively owned, vectorized float4
    for (int j = tid; j < 480; j += 256) {
        const int p   = 128 + 4 * j;
        const int fhi = p >> 6;
        const int t0  = p & 63;
        const float4 A = *(const float4*)(outb + fhi * 192 + t0);
        const float4 Bq = *(const float4*)(outb + (fhi - 1) * 192 + t0 + 64);
        const float4 C = *(const float4*)(outb + (fhi - 2) * 192 + t0 + 128);
        float4 v;
        v.x = A.x + Bq.x + C.x;
        v.y = A.y + Bq.y + C.y;
        v.z = A.z + Bq.z + C.z;
        v.w = A.w + Bq.w + C.w;
        *(float4*)(out + rowb + gb + p) = v;
    }
    // boundaries [0,128) and [2048,2176): scalar + atomic
    {
        const int p = (tid < 128) ? tid : (1920 + tid);
        const int P = gb + p;
        if (P < OUT_S) {
            const int fhi = p >> 6;
            const int t0  = p & 63;
            float v = 0.f;
            if (fhi < NFRB)  v += outb[fhi * 192 + t0];
            if (fhi >= 1 && fhi - 1 < NFRB) v += outb[(fhi - 1) * 192 + t0 + 64];
            if (fhi >= 2)    v += outb[(fhi - 2) * 192 + t0 + 128];
            atomicAdd(&out[rowb + P], v);
        }
    }
}

extern "C" void kernel_launch(void* const* d_in, const int* in_sizes, int n_in,
                              void* d_out, int out_size) {
    const float* coeff = (const float*)d_in[0];
    const float* noise = (const float*)d_in[1];
    float* out = (float*)d_out;

    cudaFuncSetAttribute(fn_main, cudaFuncAttributeMaxDynamicSharedMemorySize, SMEM_TOT);
    prep_k<<<1024, 256>>>((float4*)out);
    dim3 grid(128, B_);
    fn_main<<<grid, 256, SMEM_TOT>>>(coeff, noise, out);
}

// round 17
// speedup vs baseline: 1.1388x; 1.0920x over previous
#include <cuda_runtime.h>
#include <math.h>

typedef unsigned long long ull;
struct __align__(16) ULL2 { ull x, y; };

#define B_     64
#define F_     4097
#define FCL_   65
#define FL_    64
#define OUT_S  262144
#define NFRB   32          // frames per block
#define NWARP  8

// ---------------- packed f32x2 helpers ----------------
__device__ __forceinline__ ull fma2_(ull a, ull b, ull c) {
    ull d; asm("fma.rn.f32x2 %0,%1,%2,%3;" : "=l"(d) : "l"(a), "l"(b), "l"(c)); return d;
}
__device__ __forceinline__ ull add2_(ull a, ull b) {
    ull d; asm("add.rn.f32x2 %0,%1,%2;" : "=l"(d) : "l"(a), "l"(b)); return d;
}
__device__ __forceinline__ ull mul2_(ull a, ull b) {
    ull d; asm("mul.rn.f32x2 %0,%1,%2;" : "=l"(d) : "l"(a), "l"(b)); return d;
}
__device__ __forceinline__ ull dup_(float x) {
    ull d; unsigned r = __float_as_uint(x);
    asm("mov.b64 %0,{%1,%1};" : "=l"(d) : "r"(r)); return d;
}
__device__ __forceinline__ void unpk_(ull v, float& lo, float& hi) {
    unsigned a, b; asm("mov.b64 {%0,%1},%2;" : "=r"(a), "=r"(b) : "l"(v));
    lo = __uint_as_float(a); hi = __uint_as_float(b);
}

// ---------------- small precise tables ----------------
// g_rot[l] = (cos th1, cos th2, 2cos th1, 2cos th2), th1 = TH*(l+1), th2 = TH*(l+33)
// g_chk[j*32+l] = (cos k0*th1, cos (k0+1)*th1, cos k0*th2, cos (k0+1)*th2), k0 = 16*(j+1)
__device__ float4 g_rot[32];
__device__ float4 g_chk[3 * 32];
__device__ float  g_win[130];

// prep: build tables AND zero only the block-boundary strips of out
__global__ void prep_k(float4* __restrict__ out4) {
    const int i = blockIdx.x * blockDim.x + threadIdx.x;
    const float TH = 6.283185307179586477f / 129.0f;
    if (i < 32) {
        const int ta = i + 1, tb = i + 33;
        const float c1 = cosf(TH * (float)ta), c2 = cosf(TH * (float)tb);
        g_rot[i] = make_float4(c1, c2, 2.f * c1, 2.f * c2);
        #pragma unroll
        for (int j = 0; j < 3; j++) {
            const int k0 = 16 * (j + 1);
            g_chk[j * 32 + i] = make_float4(
                cosf(TH * (float)((k0 * ta) % 129)),
                cosf(TH * (float)(((k0 + 1) * ta) % 129)),
                cosf(TH * (float)((k0 * tb) % 129)),
                cosf(TH * (float)(((k0 + 1) * tb) % 129)));
        }
    }
    if (i < 130) g_win[i] = 0.5f - 0.5f * cosf(TH * (float)i);
    if (i < 64 * 128 * 32) {
        const int b  = i >> 12;
        const int r  = i & 4095;
        const int q  = r >> 5;
        const int j4 = r & 31;
        out4[b * 65536 + q * 512 + j4] = make_float4(0.f, 0.f, 0.f, 0.f);
    }
}

__device__ __forceinline__ float msig(float x) {
    float sg = __fdividef(1.0f, 1.0f + __expf(-x));
    return 2.0f * __powf(sg, 2.302585092994046f) + 1e-7f;
}

// ---------------- wirb XOR swizzle (16B-chunk granularity) ----------------
__device__ __forceinline__ int swz_(int c) { return c ^ ((c >> 3) & 7); }
__device__ __forceinline__ void wst_(float* wb, int i, float v) {
    int c = i >> 2;
    wb[(swz_(c) << 2) | (i & 3)] = v;
}
// masked window load: IR data lives only in chunks [16,48]; outside -> exact zeros.
// Masked lanes drop out of the address set => fewer L1 wavefronts, identical values.
__device__ __forceinline__ ULL2 wldz_(const float* wb, int c) {
    ULL2 r;
    if ((unsigned)(c - 16) <= 32u) {
        r = *(const ULL2*)(wb + (swz_(c) << 2));
    } else {
        r.x = 0ull; r.y = 0ull;
    }
    return r;
}

// ---------------- dynamic smem layout (bytes) ----------------
#define SINTJ_OFF  0        // float[8][65][4] = 8320
#define WIR_OFF    8320     // float[8][256]   = 8192 (swizzled; zero outside IR span)
#define OUTB_OFF   16512    // float[32][192]  = 24576 (x in [0..64), zp spill in [128..192))
#define SMEM_TOT   41088    // 40.1 KB -> 5 CTAs/SM

__global__ __launch_bounds__(256, 5) void fn_main(
        const float* __restrict__ coeff,   // (B, F, 65)
        const float* __restrict__ noise,   // (B, F, 64)
        float* __restrict__ out)           // (B, 262144)
{
    extern __shared__ __align__(16) char smdyn[];
    float* sIntJ = (float*)(smdyn + SINTJ_OFF);   // [w][k][ff]
    float* wirb  = (float*)(smdyn + WIR_OFF);     // [w][256] swizzled
    float* outb  = (float*)(smdyn + OUTB_OFF);    // [fi][192]

    const int tid = threadIdx.x;
    const int w   = tid >> 5;
    const int l   = tid & 31;
    const int q   = blockIdx.x;          // 0..127 (frames 0..4095; frame 4096 never contributes)
    const int b   = blockIdx.y;
    const int f0  = q * NFRB;

    // ---- stage inputs, zero wir buffers ----
    for (int i = tid; i < NWARP * 256; i += 256) wirb[i] = 0.f;
    const size_t cbo = ((size_t)b * F_ + f0) * FCL_;
    {
        int fi = tid / 65, k = tid - fi * 65;   // one division per thread
        for (int e = tid; e < NFRB * FCL_; e += 256) {
            sIntJ[(((fi & 7) * 65) + k) * 4 + (fi >> 3)] = msig(coeff[cbo + e]);
            fi += 3; k += 61;                   // 256 = 3*65 + 61
            if (k >= 65) { k -= 65; fi++; }
        }
    }
    // x staged plain into the first 64 floats of each outb row
    const size_t nbo = ((size_t)b * F_ + f0) * FL_;
    for (int e = tid; e < NFRB * FL_; e += 256) {
        int fi = e >> 6, t = e & 63;
        outb[fi * 192 + t] = 2.f * noise[nbo + e] - 1.f;
    }
    __syncthreads();

    const int t1 = l + 1, t2 = l + 33;
    float* wb = wirb + w * 256;

    // per-lane constants held in registers
    const float4 rt = __ldg(&g_rot[l]);          // (c1, c2, 2c1, 2c2)
    const float w1p = __ldg(&g_win[64 + t1]), w1m = __ldg(&g_win[64 - t1]);
    const float w2p = __ldg(&g_win[64 + t2]), w2m = __ldg(&g_win[64 - t2]);
    const float wc  = __ldg(&g_win[64]);

    // ---- cosine transform via Chebyshev 3-term recurrence (exact reseed /16 steps) ----
    // zp[t] = (s0 + 2*sum_{k=1..64} s_k cos(2pi k t/129)) / 129 ; lane handles t1, t2
    const float* sw = sIntJ + w * 65 * 4;
    ull ac0AB = 0, ac0CD = 0, ac1AB = 0, ac1CD = 0, ac2AB = 0, ac2CD = 0;
    const ULL2 s0p = *(const ULL2*)sw;
    {
        const float tc1 = rt.z, tc2 = rt.w;      // 2cos(theta)
        float cp1 = 1.f, c1 = rt.x;              // cos((k-1)th1), cos(k th1) at k=1
        float cp2 = 1.f, c2 = rt.y;
        #pragma unroll
        for (int seg = 0; seg < 4; seg++) {
            if (seg > 0) {                        // exact reseed: kills drift growth
                const float4 ck = __ldg(&g_chk[(seg - 1) * 32 + l]);
                cp1 = ck.x; c1 = ck.y; cp2 = ck.z; c2 = ck.w;
            }
            #pragma unroll
            for (int r16 = 0; r16 < 16; r16++) {
                const int k = seg * 16 + r16 + 1;
                const ULL2 sp = *(const ULL2*)(sw + k * 4);   // broadcast LDS.128
                const ull c1d = dup_(c1), c2d = dup_(c2);
                ac1AB = fma2_(sp.x, c1d, ac1AB);  ac1CD = fma2_(sp.y, c1d, ac1CD);
                ac2AB = fma2_(sp.x, c2d, ac2AB);  ac2CD = fma2_(sp.y, c2d, ac2CD);
                ac0AB = add2_(ac0AB, sp.x);       ac0CD = add2_(ac0CD, sp.y);
                const float cn1 = fmaf(tc1, c1, -cp1);   // cos((k+1)th) = 2c*ck - ck-1
                cp1 = c1; c1 = cn1;
                const float cn2 = fmaf(tc2, c2, -cp2);
                cp2 = c2; c2 = cn2;
            }
        }
    }
    const ull TWO = dup_(2.0f), SCL = dup_(1.0f / 129.0f);
    float zp0s[4];
    {
        // zp1/zp2 spill through each frame's own row tail (same-lane store/reload)
        float zA, zB;
        ull r;
        r = mul2_(fma2_(ac0AB, TWO, s0p.x), SCL); unpk_(r, zp0s[0], zp0s[1]);
        r = mul2_(fma2_(ac0CD, TWO, s0p.y), SCL); unpk_(r, zp0s[2], zp0s[3]);
        r = mul2_(fma2_(ac1AB, TWO, s0p.x), SCL); unpk_(r, zA, zB);
        outb[w * 192 + 128 + l] = zA;  outb[(8 + w) * 192 + 128 + l] = zB;
        r = mul2_(fma2_(ac1CD, TWO, s0p.y), SCL); unpk_(r, zA, zB);
        outb[(16 + w) * 192 + 128 + l] = zA;  outb[(24 + w) * 192 + 128 + l] = zB;
        r = mul2_(fma2_(ac2AB, TWO, s0p.x), SCL); unpk_(r, zA, zB);
        outb[w * 192 + 160 + l] = zA;  outb[(8 + w) * 192 + 160 + l] = zB;
        r = mul2_(fma2_(ac2CD, TWO, s0p.y), SCL); unpk_(r, zA, zB);
        outb[(16 + w) * 192 + 160 + l] = zA;  outb[(24 + w) * 192 + 160 + l] = zB;
    }

    // ---- per-frame: windowed IR build + 64x192 linear conv (dual-phase, even pairs) ----
    #pragma unroll
    for (int ff = 0; ff < 4; ff++) {
        const int fi = ff * NWARP + w;
        const float zp1 = outb[fi * 192 + 128 + l];   // same-lane reload
        const float zp2 = outb[fi * 192 + 160 + l];

        // wb[128 +/- t] = win * zp (zp even-symmetric)
        wst_(wb, 128 + t1, w1p * zp1);
        wst_(wb, 128 - t1, w1m * zp1);
        wst_(wb, 128 + t2, w2p * zp2);
        wst_(wb, 128 - t2, w2m * zp2);
        if (l == 0) wst_(wb, 128, wc * zp0s[ff]);
        __syncwarp();

        // lane ll owns outputs t = 8ll..8ll+7 (ll<24); lane 24 = boundary producer.
        const float* xs = outb + fi * 192;
        const int ll = (l < 25) ? l : 0;
        const int ll2 = 2 * ll;
        ull a0 = 0, a1 = 0, a2 = 0, a3 = 0;
        ull b0 = 0, b1 = 0, b2 = 0, b3 = 0;
        ull v0, v1, v2, v3, v4, v5;   // pairs (B-2 .. B+3), B = 32+4*ll-2g
        {
            const ULL2 pa = wldz_(wb, 15 + ll2);
            const ULL2 pb = wldz_(wb, 16 + ll2);
            const ULL2 pc = wldz_(wb, 17 + ll2);
            v0 = pa.x; v1 = pa.y; v2 = pb.x; v3 = pb.y; v4 = pc.x; v5 = pc.y;
        }
        #pragma unroll
        for (int g = 0; g < 16; g++) {
            const float4 xq = *(const float4*)(xs + 4 * g);
            const ull x0 = dup_(xq.x), x1 = dup_(xq.y), x2 = dup_(xq.z), x3 = dup_(xq.w);
            a0 = fma2_(x0, v2, a0); a1 = fma2_(x0, v3, a1);
            a2 = fma2_(x0, v4, a2); a3 = fma2_(x0, v5, a3);
            b0 = fma2_(x1, v1, b0); b1 = fma2_(x1, v2, b1);
            b2 = fma2_(x1, v3, b2); b3 = fma2_(x1, v4, b3);
            a0 = fma2_(x2, v1, a0); a1 = fma2_(x2, v2, a1);
            a2 = fma2_(x2, v3, a2); a3 = fma2_(x2, v4, a3);
            b0 = fma2_(x3, v0, b0); b1 = fma2_(x3, v1, b1);
            b2 = fma2_(x3, v2, b2); b3 = fma2_(x3, v3, b3);
            if (g < 15) {
                const ULL2 nw = wldz_(wb, 14 + ll2 - g);   // masked outside IR chunks
                v5 = v3; v4 = v2; v3 = v1; v2 = v0;
                v1 = nw.y; v0 = nw.x;
            }
        }
        // combine phases; one cross-lane boundary term via shfl
        float aL0, aH0, aL1, aH1, aL2, aH2, aL3, aH3;
        float bL0, bH0, bL1, bH1, bL2, bH2, bL3, bH3;
        unpk_(a0, aL0, aH0); unpk_(a1, aL1, aH1);
        unpk_(a2, aL2, aH2); unpk_(a3, aL3, aH3);
        unpk_(b0, bL0, bH0); unpk_(b1, bL1, bH1);
        unpk_(b2, bL2, bH2); unpk_(b3, bL3, bH3);
        const float up = __shfl_down_sync(0xffffffffu, bL0, 1);
        __syncwarp();   // all lanes' reads of wb/xs done before overwrite below / next wst
        if (l < 24) {
            float4 o03, o47;
            o03.x = aL0 + bH0; o03.y = aH0 + bL1;
            o03.z = aL1 + bH1; o03.w = aH1 + bL2;
            o47.x = aL2 + bH2; o47.y = aH2 + bL3;
            o47.z = aL3 + bH3; o47.w = aH3 + up;
            float4* op = (float4*)(outb + fi * 192 + 8 * l);
            op[0] = o03;
            op[1] = o47;
        }
        // no trailing syncwarp: next frame's wst targets wb (reads done at the sync
        // above); this row store and next frame's conv touch disjoint outb rows.
    }

    __syncthreads();

    // ---- overlap-add ----
    const size_t rowb = (size_t)b * OUT_S;
    const int gb = f0 * FL_;
    // interior [128, 2048): exclusively owned, vectorized float4
    for (int j = tid; j < 480; j += 256) {
        const int p   = 128 + 4 * j;
        const int fhi = p >> 6;
        const int t0  = p & 63;
        const float4 A = *(const float4*)(outb + fhi * 192 + t0);
        const float4 Bq = *(const float4*)(outb + (fhi - 1) * 192 + t0 + 64);
        const float4 C = *(const float4*)(outb + (fhi - 2) * 192 + t0 + 128);
        float4 v;
        v.x = A.x + Bq.x + C.x;
        v.y = A.y + Bq.y + C.y;
        v.z = A.z + Bq.z + C.z;
        v.w = A.w + Bq.w + C.w;
        *(float4*)(out + rowb + gb + p) = v;
    }
    // boundaries [0,128) and [2048,2176): scalar + atomic
    {
        const int p = (tid < 128) ? tid : (1920 + tid);
        const int P = gb + p;
        if (P < OUT_S) {
            const int fhi = p >> 6;
            const int t0  = p & 63;
            float v = 0.f;
            if (fhi < NFRB)  v += outb[fhi * 192 + t0];
            if (fhi >= 1 && fhi - 1 < NFRB) v += outb[(fhi - 1) * 192 + t0 + 64];
            if (fhi >= 2)    v += outb[(fhi - 2) * 192 + t0 + 128];
            atomicAdd(&out[rowb + P], v);
        }
    }
}

extern "C" void kernel_launch(void* const* d_in, const int* in_sizes, int n_in,
                              void* d_out, int out_size) {
    const float* coeff = (const float*)d_in[0];
    const float* noise = (const float*)d_in[1];
    float* out = (float*)d_out;

    cudaFuncSetAttribute(fn_main, cudaFuncAttributeMaxDynamicSharedMemorySize, SMEM_TOT);
    prep_k<<<1024, 256>>>((float4*)out);
    dim3 grid(128, B_);
    fn_main<<<grid, 256, SMEM_TOT>>>(coeff, noise, out);
}